// round 1
// baseline (speedup 1.0000x reference)
#include <cuda_runtime.h>

#define N2    5120      // half-length complex FFT size
#define NF    5121      // number of rfft bins of length-10240 real FFT
#define LFULL 10240
#define BATCH 32
#define CIN   128
#define COUT  128
#define TSIG  8192
#define KW    2048
#define TOUT  8193

// ---------- scratch (device globals; no runtime allocation) ----------
__device__ float2 g_Ssp[BATCH*CIN*NF];     // signal spectrum  (~168 MB)
__device__ float2 g_Wsp[COUT*CIN*NF];      // weight spectrum  (~671 MB)
__device__ float2 g_Csp[BATCH*COUT*NF];    // output spectrum  (~168 MB)
__device__ float2 g_W5120[N2];             // exp(-2πi j/5120)
__device__ float2 g_WN[NF];                // exp(-2πi k/10240)

__device__ __forceinline__ float2 cmul(float2 a, float2 b) {
    return make_float2(a.x*b.x - a.y*b.y, a.x*b.y + a.y*b.x);
}

// Storage position of true frequency k after in-place DIF with radices [4,4,4,4,4,5]
__device__ __forceinline__ int pos_of_k(int k) {
    int p = (k & 3) * 1280; k >>= 2;
    p += (k & 3) * 320;     k >>= 2;
    p += (k & 3) * 80;      k >>= 2;
    p += (k & 3) * 20;      k >>= 2;
    p += (k & 3) * 5;       k >>= 2;
    return p + k;           // k in [0,5)
}

// In-place DIF radix-4 stage over span S (M = S/4). Output digit-reversed.
template<int S>
__device__ __forceinline__ void r4_stage(float2* sm) {
    const int M  = S / 4;
    const int TW = N2 / S;
    #pragma unroll
    for (int it = 0; it < (N2/4)/256; it++) {
        int g = threadIdx.x + it*256;
        int sub = g / M;
        int j   = g - sub * M;
        int base = sub * S + j;
        float2 x0 = sm[base], x1 = sm[base+M], x2 = sm[base+2*M], x3 = sm[base+3*M];
        float2 s02 = make_float2(x0.x + x2.x, x0.y + x2.y);
        float2 d02 = make_float2(x0.x - x2.x, x0.y - x2.y);
        float2 s13 = make_float2(x1.x + x3.x, x1.y + x3.y);
        float2 d13 = make_float2(x1.x - x3.x, x1.y - x3.y);
        float2 y0 = make_float2(s02.x + s13.x, s02.y + s13.y);
        float2 y2 = make_float2(s02.x - s13.x, s02.y - s13.y);
        float2 y1 = make_float2(d02.x + d13.y, d02.y - d13.x);   // d02 - i*d13
        float2 y3 = make_float2(d02.x - d13.y, d02.y + d13.x);   // d02 + i*d13
        sm[base]       = y0;
        sm[base +   M] = cmul(y1, g_W5120[    j*TW]);
        sm[base + 2*M] = cmul(y2, g_W5120[2*j*TW]);
        sm[base + 3*M] = cmul(y3, g_W5120[3*j*TW]);
    }
    __syncthreads();
}

// Final radix-5 stage on 1024 contiguous blocks of 5 (no inter-block twiddles).
__device__ __forceinline__ void r5_stage(float2* sm) {
    const float c1 =  0.30901699437494745f, s1 = 0.9510565162951535f;
    const float c2 = -0.80901699437494734f, s2 = 0.5877852522924731f;
    #pragma unroll
    for (int it = 0; it < 1024/256; it++) {
        int g = threadIdx.x + it*256;
        int base = g * 5;
        float2 x0 = sm[base], x1 = sm[base+1], x2 = sm[base+2], x3 = sm[base+3], x4 = sm[base+4];
        float2 a1 = make_float2(x1.x + x4.x, x1.y + x4.y);
        float2 b1 = make_float2(x1.x - x4.x, x1.y - x4.y);
        float2 a2 = make_float2(x2.x + x3.x, x2.y + x3.y);
        float2 b2 = make_float2(x2.x - x3.x, x2.y - x3.y);
        float2 y0 = make_float2(x0.x + a1.x + a2.x, x0.y + a1.y + a2.y);
        float2 t1 = make_float2(x0.x + c1*a1.x + c2*a2.x, x0.y + c1*a1.y + c2*a2.y);
        float2 t2 = make_float2(x0.x + c2*a1.x + c1*a2.x, x0.y + c2*a1.y + c1*a2.y);
        float2 u1 = make_float2(s1*b1.x + s2*b2.x, s1*b1.y + s2*b2.y);
        float2 u2 = make_float2(s2*b1.x - s1*b2.x, s2*b1.y - s1*b2.y);
        sm[base]   = y0;
        sm[base+1] = make_float2(t1.x + u1.y, t1.y - u1.x);   // t1 - i*u1
        sm[base+2] = make_float2(t2.x + u2.y, t2.y - u2.x);   // t2 - i*u2
        sm[base+3] = make_float2(t2.x - u2.y, t2.y + u2.x);   // t2 + i*u2
        sm[base+4] = make_float2(t1.x - u1.y, t1.y + u1.x);   // t1 + i*u1
    }
    __syncthreads();
}

__device__ __forceinline__ void fft5120(float2* sm) {
    r4_stage<5120>(sm);
    r4_stage<1280>(sm);
    r4_stage<320>(sm);
    r4_stage<80>(sm);
    r4_stage<20>(sm);
    r5_stage(sm);
}

// ---------- twiddle init (re-run every launch; deterministic) ----------
__global__ void init_tw() {
    int j = blockIdx.x * 256 + threadIdx.x;
    const double TWO_PI = 6.283185307179586476925286766559;
    if (j < N2) {
        double a = -TWO_PI * (double)j / (double)N2;
        g_W5120[j] = make_float2((float)cos(a), (float)sin(a));
    }
    if (j < NF) {
        double a = -TWO_PI * (double)j / (double)LFULL;
        g_WN[j] = make_float2((float)cos(a), (float)sin(a));
    }
}

// ---------- forward real FFT of one row (zero-padded to 10240) ----------
// which==0: signal rows (len 8192, left pad 1024) -> g_Ssp
// which==1: weight rows (len 2048, no left pad)   -> g_Wsp
__global__ __launch_bounds__(256) void fft_fwd(const float* __restrict__ in, int rowlen, int pad, int which) {
    __shared__ float2 sm[N2];
    int row = blockIdx.x;
    const float* x = in + (long long)row * rowlen;
    for (int n = threadIdx.x; n < N2; n += 256) {
        int a0 = 2*n     - pad;
        int a1 = 2*n + 1 - pad;
        float re = (a0 >= 0 && a0 < rowlen) ? x[a0] : 0.f;
        float im = (a1 >= 0 && a1 < rowlen) ? x[a1] : 0.f;
        sm[n] = make_float2(re, im);
    }
    __syncthreads();
    fft5120(sm);

    float2* sp = (which ? g_Wsp : g_Ssp) + (long long)row * NF;
    // unpack Z (half-size complex FFT) -> X[0..5120] (rfft bins), natural order
    for (int k = threadIdx.x; k <= N2/2; k += 256) {
        float2 Zk = sm[pos_of_k(k)];
        float2 Zn = sm[pos_of_k(k == 0 ? 0 : N2 - k)];
        float2 A  = make_float2(Zk.x + Zn.x, Zk.y - Zn.y);   // Zk + conj(Zn)
        float2 Bv = make_float2(Zk.x - Zn.x, Zk.y + Zn.y);   // Zk - conj(Zn)
        float2 t  = cmul(g_WN[k], Bv);
        sp[k]      = make_float2(0.5f*(A.x + t.y),  0.5f*( A.y - t.x));
        sp[N2 - k] = make_float2(0.5f*(A.x - t.y),  0.5f*(-A.y - t.x));
    }
}

// ---------- per-frequency complex GEMM: C[b,o,f] = sum_i S[b,i,f] * conj(W[o,i,f]) ----------
__global__ __launch_bounds__(256, 1) void einsum_kernel() {
    __shared__ float2 Ssm[4][32][17];
    __shared__ float2 Wsm[4][32][17];
    int f0  = blockIdx.x * 16;
    int ob  = blockIdx.y * 32;
    int tid = threadIdx.x;
    int fl  = tid & 15;
    int wk  = tid >> 4;
    int b0  = (wk & 3) * 8;
    int oo0 = (wk >> 2) * 8;
    int f   = f0 + fl;

    float2 acc[8][8];
    #pragma unroll
    for (int i = 0; i < 8; i++)
        #pragma unroll
        for (int j = 0; j < 8; j++) acc[i][j] = make_float2(0.f, 0.f);

    for (int i0 = 0; i0 < CIN; i0 += 4) {
        __syncthreads();
        #pragma unroll
        for (int it = 0; it < 8; it++) {
            int l  = tid + it*256;
            int ff = l & 15;
            int r  = l >> 4;      // 0..127
            int ii = r >> 5;
            int rr = r & 31;
            int fg = f0 + ff;
            float2 sv = make_float2(0.f, 0.f), wv = make_float2(0.f, 0.f);
            if (fg < NF) {
                sv = g_Ssp[(long long)(rr        * CIN + i0 + ii) * NF + fg];
                wv = g_Wsp[(long long)((ob + rr) * CIN + i0 + ii) * NF + fg];
            }
            Ssm[ii][rr][ff] = sv;
            Wsm[ii][rr][ff] = wv;
        }
        __syncthreads();
        #pragma unroll
        for (int ii = 0; ii < 4; ii++) {
            float2 sf[8], wf[8];
            #pragma unroll
            for (int bb = 0; bb < 8; bb++) sf[bb] = Ssm[ii][b0 + bb][fl];
            #pragma unroll
            for (int oo = 0; oo < 8; oo++) wf[oo] = Wsm[ii][oo0 + oo][fl];
            #pragma unroll
            for (int bb = 0; bb < 8; bb++)
                #pragma unroll
                for (int oo = 0; oo < 8; oo++) {
                    acc[bb][oo].x += sf[bb].x * wf[oo].x + sf[bb].y * wf[oo].y;
                    acc[bb][oo].y += sf[bb].y * wf[oo].x - sf[bb].x * wf[oo].y;
                }
        }
    }
    if (f < NF) {
        #pragma unroll
        for (int bb = 0; bb < 8; bb++)
            #pragma unroll
            for (int oo = 0; oo < 8; oo++)
                g_Csp[(long long)((b0 + bb) * COUT + (ob + oo0 + oo)) * NF + f] = acc[bb][oo];
    }
}

// ---------- inverse real FFT + slice + bias ----------
__global__ __launch_bounds__(256) void ifft_kernel(const float* __restrict__ bias, float* __restrict__ out) {
    __shared__ float2 sm[N2];
    int row = blockIdx.x;            // b*128 + o
    int o   = row & 127;
    const float2* sp = g_Csp + (long long)row * NF;

    // repack rfft bins X[0..5120] into half-size complex spectrum; store conj(Z)
    for (int k = threadIdx.x; k < N2; k += 256) {
        float2 Xk = sp[k];
        float2 Xn = sp[N2 - k];
        float2 E  = make_float2(0.5f*(Xk.x + Xn.x), 0.5f*(Xk.y - Xn.y));
        float2 Ow = make_float2(0.5f*(Xk.x - Xn.x), 0.5f*(Xk.y + Xn.y));
        float2 w  = g_WN[k];
        float2 wc = make_float2(w.x, -w.y);            // e^{+2πik/N}
        float2 O  = cmul(Ow, wc);
        sm[k] = make_float2(E.x - O.y, -(E.y + O.x));  // conj(E + iO)
    }
    __syncthreads();
    fft5120(sm);                                       // IDFT via conj(FFT(conj(.)))/N2

    float bo = bias[o];
    float* op = out + (long long)row * TOUT;
    const float inv = 1.0f / (float)N2;
    for (int n = threadIdx.x; n < 4097; n += 256) {
        float2 v = sm[pos_of_k(n)];
        op[2*n] = v.x * inv + bo;                      // even sample, 2n <= 8192
        if (2*n + 1 < TOUT) op[2*n + 1] = -v.y * inv + bo;
    }
}

// ---------- launch ----------
extern "C" void kernel_launch(void* const* d_in, const int* in_sizes, int n_in,
                              void* d_out, int out_size) {
    const float* sig  = (const float*)d_in[0];
    const float* wgt  = (const float*)d_in[1];
    const float* bias = (const float*)d_in[2];
    float* out = (float*)d_out;

    init_tw<<<21, 256>>>();
    fft_fwd<<<BATCH*CIN, 256>>>(sig, TSIG, 1024, 0);
    fft_fwd<<<COUT*CIN,  256>>>(wgt, KW,   0,    1);
    einsum_kernel<<<dim3((NF + 15) / 16, COUT / 32), 256>>>();
    ifft_kernel<<<BATCH*COUT, 256>>>(bias, out);
    (void)in_sizes; (void)n_in; (void)out_size;
}

// round 2
// speedup vs baseline: 1.5135x; 1.5135x over previous
#include <cuda_runtime.h>
#include <cuda_fp16.h>

#define N2    5120      // half-length complex FFT size
#define NF    5121      // rfft bins of length-10240 real FFT
#define NFP   5136      // padded row length (multiple of 16)
#define LFULL 10240
#define BATCH 32
#define CIN   128
#define COUT  128
#define TSIG  8192
#define KW    2048
#define TOUT  8193

// ---------- scratch (device globals; no runtime allocation) ----------
__device__ __align__(16) __half2 g_Ssp[BATCH*CIN*NFP];   // signal spectrum (fp16)  ~84 MB
__device__ __align__(16) __half2 g_Wsp[COUT*CIN*NFP];    // weight spectrum (fp16) ~337 MB
__device__ __align__(16) float2  g_Csp[BATCH*COUT*NFP];  // output spectrum (fp32) ~168 MB
__device__ float2 g_W1280[1280];                         // e^{-2pi i j/5120}, j<1280

__device__ __forceinline__ float2 cmul(float2 a, float2 b) {
    return make_float2(a.x*b.x - a.y*b.y, a.x*b.y + a.y*b.x);
}

// Storage position of true frequency k after in-place DIF with radices [4,4,4,4,4,5]
__device__ __forceinline__ int pos_of_k(int k) {
    int p = (k & 3) * 1280; k >>= 2;
    p += (k & 3) * 320;     k >>= 2;
    p += (k & 3) * 80;      k >>= 2;
    p += (k & 3) * 20;      k >>= 2;
    p += (k & 3) * 5;       k >>= 2;
    return p + k;
}

// In-place DIF radix-4 stage over span S. w1 from L1-resident 10KB table; w2,w3 derived.
template<int S>
__device__ __forceinline__ void r4_stage(float2* sm) {
    const int M  = S / 4;
    const int TW = N2 / S;
    for (int g = threadIdx.x; g < N2/4; g += 512) {
        int sub = g / M;
        int j   = g - sub * M;
        int base = sub * S + j;
        float2 x0 = sm[base], x1 = sm[base+M], x2 = sm[base+2*M], x3 = sm[base+3*M];
        float2 s02 = make_float2(x0.x + x2.x, x0.y + x2.y);
        float2 d02 = make_float2(x0.x - x2.x, x0.y - x2.y);
        float2 s13 = make_float2(x1.x + x3.x, x1.y + x3.y);
        float2 d13 = make_float2(x1.x - x3.x, x1.y - x3.y);
        float2 y0 = make_float2(s02.x + s13.x, s02.y + s13.y);
        float2 y2 = make_float2(s02.x - s13.x, s02.y - s13.y);
        float2 y1 = make_float2(d02.x + d13.y, d02.y - d13.x);   // d02 - i*d13
        float2 y3 = make_float2(d02.x - d13.y, d02.y + d13.x);   // d02 + i*d13
        float2 w1 = g_W1280[j * TW];
        float2 w2 = cmul(w1, w1);
        float2 w3 = cmul(w2, w1);
        sm[base]       = y0;
        sm[base +   M] = cmul(y1, w1);
        sm[base + 2*M] = cmul(y2, w2);
        sm[base + 3*M] = cmul(y3, w3);
    }
    __syncthreads();
}

__device__ __forceinline__ void r5_stage(float2* sm) {
    const float c1 =  0.30901699437494745f, s1 = 0.9510565162951535f;
    const float c2 = -0.80901699437494734f, s2 = 0.5877852522924731f;
    for (int g = threadIdx.x; g < 1024; g += 512) {
        int base = g * 5;
        float2 x0 = sm[base], x1 = sm[base+1], x2 = sm[base+2], x3 = sm[base+3], x4 = sm[base+4];
        float2 a1 = make_float2(x1.x + x4.x, x1.y + x4.y);
        float2 b1 = make_float2(x1.x - x4.x, x1.y - x4.y);
        float2 a2 = make_float2(x2.x + x3.x, x2.y + x3.y);
        float2 b2 = make_float2(x2.x - x3.x, x2.y - x3.y);
        float2 y0 = make_float2(x0.x + a1.x + a2.x, x0.y + a1.y + a2.y);
        float2 t1 = make_float2(x0.x + c1*a1.x + c2*a2.x, x0.y + c1*a1.y + c2*a2.y);
        float2 t2 = make_float2(x0.x + c2*a1.x + c1*a2.x, x0.y + c2*a1.y + c1*a2.y);
        float2 u1 = make_float2(s1*b1.x + s2*b2.x, s1*b1.y + s2*b2.y);
        float2 u2 = make_float2(s2*b1.x - s1*b2.x, s2*b1.y - s1*b2.y);
        sm[base]   = y0;
        sm[base+1] = make_float2(t1.x + u1.y, t1.y - u1.x);
        sm[base+2] = make_float2(t2.x + u2.y, t2.y - u2.x);
        sm[base+3] = make_float2(t2.x - u2.y, t2.y + u2.x);
        sm[base+4] = make_float2(t1.x - u1.y, t1.y + u1.x);
    }
    __syncthreads();
}

__global__ void init_tw() {
    int j = blockIdx.x * 256 + threadIdx.x;
    if (j < 1280) {
        double a = -6.283185307179586476925286766559 * (double)j / 5120.0;
        g_W1280[j] = make_float2((float)cos(a), (float)sin(a));
    }
}

// unpack the half-size complex FFT result into rfft bins (fp16 out, padded row)
__device__ __forceinline__ void unpack_store(float2* sm, __half2* sp) {
    for (int k = threadIdx.x; k <= N2/2; k += 512) {
        float2 Zk = sm[pos_of_k(k)];
        float2 Zn = sm[pos_of_k(k == 0 ? 0 : N2 - k)];
        float2 A  = make_float2(Zk.x + Zn.x, Zk.y - Zn.y);
        float2 Bv = make_float2(Zk.x - Zn.x, Zk.y + Zn.y);
        float sn, cs;
        __sincosf(-6.2831853071795864769f * (float)k / (float)LFULL, &sn, &cs);
        float2 t = cmul(make_float2(cs, sn), Bv);
        sp[k]      = __floats2half2_rn(0.5f*(A.x + t.y),  0.5f*( A.y - t.x));
        sp[N2 - k] = __floats2half2_rn(0.5f*(A.x - t.y),  0.5f*(-A.y - t.x));
    }
    for (int k = NF + threadIdx.x; k < NFP; k += 512)
        sp[k] = __floats2half2_rn(0.f, 0.f);
}

// ---------- forward FFT: signal rows (len 8192, left pad 1024) ----------
__global__ __launch_bounds__(512) void fft_sig(const float* __restrict__ in) {
    __shared__ float2 sm[N2];
    int row = blockIdx.x;
    const float* x = in + (long long)row * TSIG;
    for (int n = threadIdx.x; n < N2; n += 512) {
        int a0 = 2*n     - 1024;
        int a1 = 2*n + 1 - 1024;
        float re = (a0 >= 0 && a0 < TSIG) ? x[a0] : 0.f;
        float im = (a1 >= 0 && a1 < TSIG) ? x[a1] : 0.f;
        sm[n] = make_float2(re, im);
    }
    __syncthreads();
    r4_stage<5120>(sm);
    r4_stage<1280>(sm);
    r4_stage<320>(sm);
    r4_stage<80>(sm);
    r4_stage<20>(sm);
    r5_stage(sm);
    unpack_store(sm, g_Ssp + (long long)row * NFP);
}

// ---------- forward FFT: weight rows (len 2048 => stage 1 fused into load) ----------
__global__ __launch_bounds__(512) void fft_wgt(const float* __restrict__ in) {
    __shared__ float2 sm[N2];
    int row = blockIdx.x;
    const float* x = in + (long long)row * KW;
    // input occupies complex slots [0,1024); stage-1 butterfly is y0=y1=y2=y3=x0
    for (int j = threadIdx.x; j < 1280; j += 512) {
        float2 x0 = make_float2(0.f, 0.f);
        if (j < 1024) x0 = make_float2(x[2*j], x[2*j + 1]);
        float2 w1 = g_W1280[j];
        float2 w2 = cmul(w1, w1);
        float2 w3 = cmul(w2, w1);
        sm[j]        = x0;
        sm[j + 1280] = cmul(x0, w1);
        sm[j + 2560] = cmul(x0, w2);
        sm[j + 3840] = cmul(x0, w3);
    }
    __syncthreads();
    r4_stage<1280>(sm);
    r4_stage<320>(sm);
    r4_stage<80>(sm);
    r4_stage<20>(sm);
    r5_stage(sm);
    unpack_store(sm, g_Wsp + (long long)row * NFP);
}

// ---------- per-frequency complex GEMM: C[b,o,f] = sum_i S[b,i,f] * conj(W[o,i,f]) ----------
__device__ __forceinline__ void cp8(void* dst_smem, const void* src) {
    unsigned long long sa = __cvta_generic_to_shared(dst_smem);
    asm volatile("cp.async.ca.shared.global [%0], [%1], 8;\n"
                 :: "r"((unsigned)sa), "l"(src));
}

__global__ __launch_bounds__(512, 1) void einsum_kernel() {
    __shared__ __half2 Ssm[2][4][32][18];
    __shared__ __half2 Wsm[2][4][32][18];
    int ob  = blockIdx.x * 32;
    int f0  = blockIdx.y * 16;
    int tid = threadIdx.x;
    int fl  = tid & 15;
    int wk  = tid >> 4;
    int b0  = (wk & 3) * 8;
    int oo0 = (wk >> 2) * 4;

    const int NT = CIN / 4;   // 32 k-tiles

    // fill one (buf, k-tile): 1024 8-byte chunks per array, 512 threads => 2 each
    auto fill = [&](int buf, int i0) {
        #pragma unroll
        for (int u = 0; u < 2; u++) {
            int c  = tid + u * 512;
            int ff = (c & 7) * 2;
            int r  = c >> 3;
            int ii = r >> 5;
            int rr = r & 31;
            cp8(&Ssm[buf][ii][rr][ff], &g_Ssp[(long long)(rr        * CIN + i0 + ii) * NFP + f0 + ff]);
            cp8(&Wsm[buf][ii][rr][ff], &g_Wsp[(long long)((ob + rr) * CIN + i0 + ii) * NFP + f0 + ff]);
        }
        asm volatile("cp.async.commit_group;\n");
    };

    float2 acc[8][4];
    #pragma unroll
    for (int i = 0; i < 8; i++)
        #pragma unroll
        for (int j = 0; j < 4; j++) acc[i][j] = make_float2(0.f, 0.f);

    fill(0, 0);
    fill(1, 4);

    int cur = 0;
    for (int t = 0; t < NT; t++) {
        if (t < NT - 1) asm volatile("cp.async.wait_group 1;\n");
        else            asm volatile("cp.async.wait_group 0;\n");
        __syncthreads();

        #pragma unroll
        for (int ii = 0; ii < 4; ii++) {
            float2 sf[8], wf[4];
            #pragma unroll
            for (int bb = 0; bb < 8; bb++) sf[bb] = __half22float2(Ssm[cur][ii][b0 + bb][fl]);
            #pragma unroll
            for (int oo = 0; oo < 4; oo++) wf[oo] = __half22float2(Wsm[cur][ii][oo0 + oo][fl]);
            #pragma unroll
            for (int bb = 0; bb < 8; bb++)
                #pragma unroll
                for (int oo = 0; oo < 4; oo++) {
                    acc[bb][oo].x += sf[bb].x * wf[oo].x + sf[bb].y * wf[oo].y;
                    acc[bb][oo].y += sf[bb].y * wf[oo].x - sf[bb].x * wf[oo].y;
                }
        }
        __syncthreads();
        if (t + 2 < NT) fill(cur, (t + 2) * 4);
        cur ^= 1;
    }

    #pragma unroll
    for (int bb = 0; bb < 8; bb++)
        #pragma unroll
        for (int oo = 0; oo < 4; oo++)
            g_Csp[(long long)((b0 + bb) * COUT + (ob + oo0 + oo)) * NFP + f0 + fl] = acc[bb][oo];
}

// ---------- inverse real FFT + slice + bias ----------
__global__ __launch_bounds__(512) void ifft_kernel(const float* __restrict__ bias, float* __restrict__ out) {
    __shared__ float2 sm[N2];
    int row = blockIdx.x;            // b*128 + o
    int o   = row & 127;
    const float2* sp = g_Csp + (long long)row * NFP;

    for (int k = threadIdx.x; k < N2; k += 512) {
        float2 Xk = sp[k];
        float2 Xn = sp[N2 - k];
        float2 E  = make_float2(0.5f*(Xk.x + Xn.x), 0.5f*(Xk.y - Xn.y));
        float2 Ow = make_float2(0.5f*(Xk.x - Xn.x), 0.5f*(Xk.y + Xn.y));
        float sn, cs;
        __sincosf(6.2831853071795864769f * (float)k / (float)LFULL, &sn, &cs);
        float2 O  = cmul(Ow, make_float2(cs, sn));     // e^{+2pi i k/N}
        sm[k] = make_float2(E.x - O.y, -(E.y + O.x));  // conj(E + iO)
    }
    __syncthreads();
    r4_stage<5120>(sm);
    r4_stage<1280>(sm);
    r4_stage<320>(sm);
    r4_stage<80>(sm);
    r4_stage<20>(sm);
    r5_stage(sm);

    float bo = bias[o];
    float* op = out + (long long)row * TOUT;
    const float inv = 1.0f / (float)N2;
    for (int n = threadIdx.x; n < 4097; n += 512) {
        float2 v = sm[pos_of_k(n)];
        op[2*n] = v.x * inv + bo;
        if (2*n + 1 < TOUT) op[2*n + 1] = -v.y * inv + bo;
    }
}

// ---------- launch ----------
extern "C" void kernel_launch(void* const* d_in, const int* in_sizes, int n_in,
                              void* d_out, int out_size) {
    const float* sig  = (const float*)d_in[0];
    const float* wgt  = (const float*)d_in[1];
    const float* bias = (const float*)d_in[2];
    float* out = (float*)d_out;

    init_tw<<<5, 256>>>();
    fft_sig<<<BATCH*CIN, 512>>>(sig);
    fft_wgt<<<COUT*CIN,  512>>>(wgt);
    einsum_kernel<<<dim3(COUT/32, NFP/16), 512>>>();
    ifft_kernel<<<BATCH*COUT, 512>>>(bias, out);
    (void)in_sizes; (void)n_in; (void)out_size;
}

// round 4
// speedup vs baseline: 1.8943x; 1.2516x over previous
#include <cuda_runtime.h>
#include <cuda_fp16.h>
#include <cstdint>

#define N2    5120
#define NF    5121
#define NFP   5136
#define LFULL 10240
#define BATCH 32
#define CIN   128
#define COUT  128
#define TSIG  8192
#define KW    2048
#define TOUT  8193

#define FPB   4
#define NCTA  ((NF + FPB - 1) / FPB)   // 1281

// ---------- scratch ----------
__device__ __align__(16) __half2 g_Ssp [BATCH*CIN*NFP];   // (re,im)
__device__ __align__(16) __half2 g_Ssp2[BATCH*CIN*NFP];   // (im,-re)
__device__ __align__(16) __half2 g_Wsp [COUT*CIN*NFP];    // (re,im)
__device__ __align__(16) float2  g_Csp [BATCH*COUT*NFP];
__device__ float2 g_W1280[1280];

__device__ __forceinline__ float2 cmul(float2 a, float2 b) {
    return make_float2(a.x*b.x - a.y*b.y, a.x*b.y + a.y*b.x);
}

__device__ __forceinline__ int pos_of_k(int k) {
    int p = (k & 3) * 1280; k >>= 2;
    p += (k & 3) * 320;     k >>= 2;
    p += (k & 3) * 80;      k >>= 2;
    p += (k & 3) * 20;      k >>= 2;
    p += (k & 3) * 5;       k >>= 2;
    return p + k;
}

template<int S>
__device__ __forceinline__ void r4_stage(float2* sm) {
    const int M  = S / 4;
    const int TW = N2 / S;
    for (int g = threadIdx.x; g < N2/4; g += 512) {
        int sub = g / M;
        int j   = g - sub * M;
        int base = sub * S + j;
        float2 x0 = sm[base], x1 = sm[base+M], x2 = sm[base+2*M], x3 = sm[base+3*M];
        float2 s02 = make_float2(x0.x + x2.x, x0.y + x2.y);
        float2 d02 = make_float2(x0.x - x2.x, x0.y - x2.y);
        float2 s13 = make_float2(x1.x + x3.x, x1.y + x3.y);
        float2 d13 = make_float2(x1.x - x3.x, x1.y - x3.y);
        float2 y0 = make_float2(s02.x + s13.x, s02.y + s13.y);
        float2 y2 = make_float2(s02.x - s13.x, s02.y - s13.y);
        float2 y1 = make_float2(d02.x + d13.y, d02.y - d13.x);
        float2 y3 = make_float2(d02.x - d13.y, d02.y + d13.x);
        float2 w1 = g_W1280[j * TW];
        float2 w2 = cmul(w1, w1);
        float2 w3 = cmul(w2, w1);
        sm[base]       = y0;
        sm[base +   M] = cmul(y1, w1);
        sm[base + 2*M] = cmul(y2, w2);
        sm[base + 3*M] = cmul(y3, w3);
    }
    __syncthreads();
}

__device__ __forceinline__ void r5_stage(float2* sm) {
    const float c1 =  0.30901699437494745f, s1 = 0.9510565162951535f;
    const float c2 = -0.80901699437494734f, s2 = 0.5877852522924731f;
    for (int g = threadIdx.x; g < 1024; g += 512) {
        int base = g * 5;
        float2 x0 = sm[base], x1 = sm[base+1], x2 = sm[base+2], x3 = sm[base+3], x4 = sm[base+4];
        float2 a1 = make_float2(x1.x + x4.x, x1.y + x4.y);
        float2 b1 = make_float2(x1.x - x4.x, x1.y - x4.y);
        float2 a2 = make_float2(x2.x + x3.x, x2.y + x3.y);
        float2 b2 = make_float2(x2.x - x3.x, x2.y - x3.y);
        float2 y0 = make_float2(x0.x + a1.x + a2.x, x0.y + a1.y + a2.y);
        float2 t1 = make_float2(x0.x + c1*a1.x + c2*a2.x, x0.y + c1*a1.y + c2*a2.y);
        float2 t2 = make_float2(x0.x + c2*a1.x + c1*a2.x, x0.y + c2*a1.y + c1*a2.y);
        float2 u1 = make_float2(s1*b1.x + s2*b2.x, s1*b1.y + s2*b2.y);
        float2 u2 = make_float2(s2*b1.x - s1*b2.x, s2*b1.y - s1*b2.y);
        sm[base]   = y0;
        sm[base+1] = make_float2(t1.x + u1.y, t1.y - u1.x);
        sm[base+2] = make_float2(t2.x + u2.y, t2.y - u2.x);
        sm[base+3] = make_float2(t2.x - u2.y, t2.y + u2.x);
        sm[base+4] = make_float2(t1.x - u1.y, t1.y + u1.x);
    }
    __syncthreads();
}

__global__ void init_tw() {
    int j = blockIdx.x * 256 + threadIdx.x;
    if (j < 1280) {
        double a = -6.283185307179586476925286766559 * (double)j / 5120.0;
        g_W1280[j] = make_float2((float)cos(a), (float)sin(a));
    }
}

// ---------- forward FFT: signal rows (writes both S planes) ----------
__global__ __launch_bounds__(512) void fft_sig(const float* __restrict__ in) {
    __shared__ float2 sm[N2];
    int row = blockIdx.x;
    const float* x = in + (long long)row * TSIG;
    for (int n = threadIdx.x; n < N2; n += 512) {
        int a0 = 2*n     - 1024;
        int a1 = 2*n + 1 - 1024;
        float re = (a0 >= 0 && a0 < TSIG) ? x[a0] : 0.f;
        float im = (a1 >= 0 && a1 < TSIG) ? x[a1] : 0.f;
        sm[n] = make_float2(re, im);
    }
    __syncthreads();
    r4_stage<5120>(sm); r4_stage<1280>(sm); r4_stage<320>(sm);
    r4_stage<80>(sm);   r4_stage<20>(sm);   r5_stage(sm);

    __half2* sp1 = g_Ssp  + (long long)row * NFP;
    __half2* sp2 = g_Ssp2 + (long long)row * NFP;
    for (int k = threadIdx.x; k <= N2/2; k += 512) {
        float2 Zk = sm[pos_of_k(k)];
        float2 Zn = sm[pos_of_k(k == 0 ? 0 : N2 - k)];
        float2 A  = make_float2(Zk.x + Zn.x, Zk.y - Zn.y);
        float2 Bv = make_float2(Zk.x - Zn.x, Zk.y + Zn.y);
        float sn, cs;
        __sincosf(-6.2831853071795864769f * (float)k / (float)LFULL, &sn, &cs);
        float2 t = cmul(make_float2(cs, sn), Bv);
        float r0 = 0.5f*(A.x + t.y), i0v =  0.5f*( A.y - t.x);
        float r1 = 0.5f*(A.x - t.y), i1v =  0.5f*(-A.y - t.x);
        sp1[k]      = __floats2half2_rn(r0, i0v);
        sp1[N2 - k] = __floats2half2_rn(r1, i1v);
        sp2[k]      = __floats2half2_rn(i0v, -r0);
        sp2[N2 - k] = __floats2half2_rn(i1v, -r1);
    }
    for (int k = NF + threadIdx.x; k < NFP; k += 512) {
        sp1[k] = __floats2half2_rn(0.f, 0.f);
        sp2[k] = __floats2half2_rn(0.f, 0.f);
    }
}

// ---------- forward FFT: weight rows ----------
__global__ __launch_bounds__(512) void fft_wgt(const float* __restrict__ in) {
    __shared__ float2 sm[N2];
    int row = blockIdx.x;
    const float* x = in + (long long)row * KW;
    for (int j = threadIdx.x; j < 1280; j += 512) {
        float2 x0 = make_float2(0.f, 0.f);
        if (j < 1024) x0 = make_float2(x[2*j], x[2*j + 1]);
        float2 w1 = g_W1280[j];
        float2 w2 = cmul(w1, w1);
        float2 w3 = cmul(w2, w1);
        sm[j]        = x0;
        sm[j + 1280] = cmul(x0, w1);
        sm[j + 2560] = cmul(x0, w2);
        sm[j + 3840] = cmul(x0, w3);
    }
    __syncthreads();
    r4_stage<1280>(sm); r4_stage<320>(sm); r4_stage<80>(sm);
    r4_stage<20>(sm);   r5_stage(sm);

    __half2* sp = g_Wsp + (long long)row * NFP;
    for (int k = threadIdx.x; k <= N2/2; k += 512) {
        float2 Zk = sm[pos_of_k(k)];
        float2 Zn = sm[pos_of_k(k == 0 ? 0 : N2 - k)];
        float2 A  = make_float2(Zk.x + Zn.x, Zk.y - Zn.y);
        float2 Bv = make_float2(Zk.x - Zn.x, Zk.y + Zn.y);
        float sn, cs;
        __sincosf(-6.2831853071795864769f * (float)k / (float)LFULL, &sn, &cs);
        float2 t = cmul(make_float2(cs, sn), Bv);
        sp[k]      = __floats2half2_rn(0.5f*(A.x + t.y),  0.5f*( A.y - t.x));
        sp[N2 - k] = __floats2half2_rn(0.5f*(A.x - t.y),  0.5f*(-A.y - t.x));
    }
    for (int k = NF + threadIdx.x; k < NFP; k += 512)
        sp[k] = __floats2half2_rn(0.f, 0.f);
}

// ================= HMMA einsum (mma.sync, base PTX ISA) =================
// Per CTA: 4 frequencies. For each f: D[128(o) x 64(n)] = A[128 x 256] * B[64 x 256]^T
// where k interleaves (re,im) over 128 input channels; n = b (plane0 -> C_re)
// or b+32 (plane1 -> C_im).
__device__ __forceinline__ uint32_t smem_u32(const void* p) {
    uint32_t a;
    asm("{ .reg .u64 t; cvta.to.shared.u64 t, %1; cvt.u32.u64 %0, t; }" : "=r"(a) : "l"(p));
    return a;
}

#define WOFF 0
#define SOFF (64*1024)
#define EIN_SMEM (96*1024)

__global__ __launch_bounds__(256, 1) void einsum_mma() {
    extern __shared__ __align__(1024) char smem[];
    const uint32_t sbase = smem_u32(smem);
    const int tid  = threadIdx.x;
    const int lane = tid & 31;
    const int w    = tid >> 5;          // 8 warps
    const int fl   = w >> 1;            // f within CTA
    const int m0   = (w & 1) * 64;      // o half
    const int f0   = blockIdx.x * FPB;

    const uint32_t Atile = sbase + WOFF + fl * 16384;   // [128 o][128B]
    const uint32_t Btile = sbase + SOFF + fl * 8192;    // [64 n][128B]
    const uint32_t sw    = (lane & 7) << 4;
    const uint32_t a_row = Atile + (m0 + (lane & 15)) * 128;
    const uint32_t b_row = Btile + (lane & 7) * 128;

    float acc[4][8][4];
    #pragma unroll
    for (int i = 0; i < 4; i++)
        #pragma unroll
        for (int j = 0; j < 8; j++)
            #pragma unroll
            for (int q = 0; q < 4; q++) acc[i][j][q] = 0.f;

    for (int c = 0; c < 4; c++) {
        const int i0 = c * 32;
        // ---- stage W: 4096 rows x 16B (4 f half2) ----
        #pragma unroll
        for (int it = 0; it < 16; it++) {
            int r  = tid + it * 256;
            int o  = r >> 5, il = r & 31;
            uint4 v = *(const uint4*)(g_Wsp + (long long)(o*CIN + i0 + il) * NFP + f0);
            uint32_t base = WOFF + o * 128 + ((il * 4) ^ ((o & 7) << 4));
            *(uint32_t*)(smem + base)             = v.x;
            *(uint32_t*)(smem + base + 16384)     = v.y;
            *(uint32_t*)(smem + base + 2*16384)   = v.z;
            *(uint32_t*)(smem + base + 3*16384)   = v.w;
        }
        // ---- stage S: 2048 rows (2 planes x 32 b x 32 i) ----
        #pragma unroll
        for (int it = 0; it < 8; it++) {
            int r   = tid + it * 256;
            int pl  = r >> 10, b = (r >> 5) & 31, il = r & 31;
            const __half2* gs = (pl ? g_Ssp2 : g_Ssp) + (long long)(b*CIN + i0 + il) * NFP + f0;
            uint4 v = *(const uint4*)gs;
            int n = pl * 32 + b;
            uint32_t base = SOFF + n * 128 + ((il * 4) ^ ((n & 7) << 4));
            *(uint32_t*)(smem + base)            = v.x;
            *(uint32_t*)(smem + base + 8192)     = v.y;
            *(uint32_t*)(smem + base + 2*8192)   = v.z;
            *(uint32_t*)(smem + base + 3*8192)   = v.w;
        }
        __syncthreads();

        // ---- compute: K = 64 halfs in 4 k16 steps ----
        #pragma unroll
        for (int ks = 0; ks < 4; ks++) {
            uint32_t acb = (ks*32 + (lane >> 4)*16) ^ sw;
            uint32_t bcb = (ks*32 + ((lane >> 3) & 1)*16) ^ sw;
            uint32_t bfr[8][2];
            #pragma unroll
            for (int ni = 0; ni < 8; ni++) {
                asm volatile("ldmatrix.sync.aligned.m8n8.x2.shared.b16 {%0,%1}, [%2];"
                             : "=r"(bfr[ni][0]), "=r"(bfr[ni][1])
                             : "r"(b_row + ni*1024 + bcb));
            }
            #pragma unroll
            for (int mi = 0; mi < 4; mi++) {
                uint32_t a0, a1, a2, a3;
                asm volatile("ldmatrix.sync.aligned.m8n8.x4.shared.b16 {%0,%1,%2,%3}, [%4];"
                             : "=r"(a0), "=r"(a1), "=r"(a2), "=r"(a3)
                             : "r"(a_row + mi*2048 + acb));
                #pragma unroll
                for (int ni = 0; ni < 8; ni++) {
                    asm volatile(
                        "mma.sync.aligned.m16n8k16.row.col.f32.f16.f16.f32 "
                        "{%0,%1,%2,%3}, {%4,%5,%6,%7}, {%8,%9}, {%0,%1,%2,%3};"
                        : "+f"(acc[mi][ni][0]), "+f"(acc[mi][ni][1]),
                          "+f"(acc[mi][ni][2]), "+f"(acc[mi][ni][3])
                        : "r"(a0), "r"(a1), "r"(a2), "r"(a3),
                          "r"(bfr[ni][0]), "r"(bfr[ni][1]));
                }
            }
        }
        __syncthreads();
    }

    // ---- epilogue: 2 passes over o-halves; stage [b=32][o=64][f=4] float2 ----
    float2* stg = (float2*)smem;
    for (int p = 0; p < 2; p++) {
        if ((w & 1) == p) {
            #pragma unroll
            for (int mi = 0; mi < 4; mi++)
                #pragma unroll
                for (int ni = 0; ni < 4; ni++)
                    #pragma unroll
                    for (int j = 0; j < 4; j++) {
                        int b  = ni*8 + (lane & 3)*2 + (j & 1);
                        int ol = mi*16 + (lane >> 2) + 8*(j >> 1);
                        stg[(b*64 + ol)*4 + fl] =
                            make_float2(acc[mi][ni][j], acc[mi][ni + 4][j]);
                    }
        }
        __syncthreads();
        #pragma unroll
        for (int it = 0; it < 16; it++) {
            int u   = tid + it * 256;          // 4096 16B units
            int row = u >> 1, hf = u & 1;      // row = b*64 + o_local
            int b = row >> 6, ol = row & 63;
            const uint4 v = *(const uint4*)&stg[row*4 + hf*2];
            *(uint4*)(g_Csp + (long long)(b*COUT + p*64 + ol) * NFP + f0 + hf*2) = v;
        }
        __syncthreads();
    }
}

// ---------- inverse real FFT + slice + bias ----------
__global__ __launch_bounds__(512) void ifft_kernel(const float* __restrict__ bias, float* __restrict__ out) {
    __shared__ float2 sm[N2];
    int row = blockIdx.x;
    int o   = row & 127;
    const float2* sp = g_Csp + (long long)row * NFP;

    for (int k = threadIdx.x; k < N2; k += 512) {
        float2 Xk = sp[k];
        float2 Xn = sp[N2 - k];
        float2 E  = make_float2(0.5f*(Xk.x + Xn.x), 0.5f*(Xk.y - Xn.y));
        float2 Ow = make_float2(0.5f*(Xk.x - Xn.x), 0.5f*(Xk.y + Xn.y));
        float sn, cs;
        __sincosf(6.2831853071795864769f * (float)k / (float)LFULL, &sn, &cs);
        float2 O  = cmul(Ow, make_float2(cs, sn));
        sm[k] = make_float2(E.x - O.y, -(E.y + O.x));
    }
    __syncthreads();
    r4_stage<5120>(sm); r4_stage<1280>(sm); r4_stage<320>(sm);
    r4_stage<80>(sm);   r4_stage<20>(sm);   r5_stage(sm);

    float bo = bias[o];
    float* op = out + (long long)row * TOUT;
    const float inv = 1.0f / (float)N2;
    for (int n = threadIdx.x; n < 4097; n += 512) {
        float2 v = sm[pos_of_k(n)];
        op[2*n] = v.x * inv + bo;
        if (2*n + 1 < TOUT) op[2*n + 1] = -v.y * inv + bo;
    }
}

// ---------- launch ----------
extern "C" void kernel_launch(void* const* d_in, const int* in_sizes, int n_in,
                              void* d_out, int out_size) {
    const float* sig  = (const float*)d_in[0];
    const float* wgt  = (const float*)d_in[1];
    const float* bias = (const float*)d_in[2];
    float* out = (float*)d_out;

    cudaFuncSetAttribute(einsum_mma, cudaFuncAttributeMaxDynamicSharedMemorySize, EIN_SMEM);

    init_tw<<<5, 256>>>();
    fft_sig<<<BATCH*CIN, 512>>>(sig);
    fft_wgt<<<COUT*CIN,  512>>>(wgt);
    einsum_mma<<<NCTA, 256, EIN_SMEM>>>();
    ifft_kernel<<<BATCH*COUT, 512>>>(bias, out);
    (void)in_sizes; (void)n_in; (void)out_size;
}

// round 5
// speedup vs baseline: 2.0445x; 1.0793x over previous
#include <cuda_runtime.h>
#include <cuda_fp16.h>
#include <cstdint>

#define N2    5120
#define NF    5121
#define NFP   5136
#define LFULL 10240
#define BATCH 32
#define CIN   128
#define COUT  128
#define TSIG  8192
#define KW    2048
#define TOUT  8193

#define FPB   4
#define NCTA  ((NF + FPB - 1) / FPB)   // 1281

// ---------- scratch ----------
// K-major tiled spectra: element (row, i, f) stored at ((row*32 + (i>>2))*NFP + f)*4 + (i&3)
__device__ __align__(16) __half2 g_Ssp [BATCH*CIN*NFP];   // (re,im)
__device__ __align__(16) __half2 g_Ssp2[BATCH*CIN*NFP];   // (im,-re)
__device__ __align__(16) __half2 g_Wsp [COUT*CIN*NFP];    // (re,im)
__device__ __align__(16) float2  g_Csp [BATCH*COUT*NFP];
// twiddle triplets per stage: [w1.x w1.y w2.x w2.y] + [w3.x w3.y]
__device__ float4 g_TWa[1705];
__device__ float2 g_TWb[1705];

__device__ __forceinline__ float2 cmul(float2 a, float2 b) {
    return make_float2(a.x*b.x - a.y*b.y, a.x*b.y + a.y*b.x);
}

__device__ __forceinline__ int pos_of_k(int k) {
    int p = (k & 3) * 1280; k >>= 2;
    p += (k & 3) * 320;     k >>= 2;
    p += (k & 3) * 80;      k >>= 2;
    p += (k & 3) * 20;      k >>= 2;
    p += (k & 3) * 5;       k >>= 2;
    return p + k;
}

// In-place DIF radix-4 stage; twiddles from precomputed table at OFF.
template<int S, int OFF>
__device__ __forceinline__ void r4_stage(float2* sm) {
    const int M = S / 4;
    for (int g = threadIdx.x; g < N2/4; g += 512) {
        int sub = g / M;
        int j   = g - sub * M;
        int base = sub * S + j;
        float2 x0 = sm[base], x1 = sm[base+M], x2 = sm[base+2*M], x3 = sm[base+3*M];
        float2 s02 = make_float2(x0.x + x2.x, x0.y + x2.y);
        float2 d02 = make_float2(x0.x - x2.x, x0.y - x2.y);
        float2 s13 = make_float2(x1.x + x3.x, x1.y + x3.y);
        float2 d13 = make_float2(x1.x - x3.x, x1.y - x3.y);
        float2 y0 = make_float2(s02.x + s13.x, s02.y + s13.y);
        float2 y2 = make_float2(s02.x - s13.x, s02.y - s13.y);
        float2 y1 = make_float2(d02.x + d13.y, d02.y - d13.x);
        float2 y3 = make_float2(d02.x - d13.y, d02.y + d13.x);
        float4 wa = g_TWa[OFF + j];
        float2 w3 = g_TWb[OFF + j];
        sm[base]       = y0;
        sm[base +   M] = cmul(y1, make_float2(wa.x, wa.y));
        sm[base + 2*M] = cmul(y2, make_float2(wa.z, wa.w));
        sm[base + 3*M] = cmul(y3, w3);
    }
    __syncthreads();
}

__device__ __forceinline__ void r5_stage(float2* sm) {
    const float c1 =  0.30901699437494745f, s1 = 0.9510565162951535f;
    const float c2 = -0.80901699437494734f, s2 = 0.5877852522924731f;
    for (int g = threadIdx.x; g < 1024; g += 512) {
        int base = g * 5;
        float2 x0 = sm[base], x1 = sm[base+1], x2 = sm[base+2], x3 = sm[base+3], x4 = sm[base+4];
        float2 a1 = make_float2(x1.x + x4.x, x1.y + x4.y);
        float2 b1 = make_float2(x1.x - x4.x, x1.y - x4.y);
        float2 a2 = make_float2(x2.x + x3.x, x2.y + x3.y);
        float2 b2 = make_float2(x2.x - x3.x, x2.y - x3.y);
        float2 y0 = make_float2(x0.x + a1.x + a2.x, x0.y + a1.y + a2.y);
        float2 t1 = make_float2(x0.x + c1*a1.x + c2*a2.x, x0.y + c1*a1.y + c2*a2.y);
        float2 t2 = make_float2(x0.x + c2*a1.x + c1*a2.x, x0.y + c2*a1.y + c1*a2.y);
        float2 u1 = make_float2(s1*b1.x + s2*b2.x, s1*b1.y + s2*b2.y);
        float2 u2 = make_float2(s2*b1.x - s1*b2.x, s2*b1.y - s1*b2.y);
        sm[base]   = y0;
        sm[base+1] = make_float2(t1.x + u1.y, t1.y - u1.x);
        sm[base+2] = make_float2(t2.x + u2.y, t2.y - u2.x);
        sm[base+3] = make_float2(t2.x - u2.y, t2.y + u2.x);
        sm[base+4] = make_float2(t1.x - u1.y, t1.y + u1.x);
    }
    __syncthreads();
}

__global__ void init_tw() {
    int t = blockIdx.x * 256 + threadIdx.x;
    if (t < 1705) {
        int off, tw;
        if      (t < 1280) { off = 0;    tw = 1;   }
        else if (t < 1600) { off = 1280; tw = 4;   }
        else if (t < 1680) { off = 1600; tw = 16;  }
        else if (t < 1700) { off = 1680; tw = 64;  }
        else               { off = 1700; tw = 256; }
        int j = t - off;
        double a = -6.283185307179586476925286766559 * (double)(j * tw) / 5120.0;
        g_TWa[t] = make_float4((float)cos(a),   (float)sin(a),
                               (float)cos(2*a), (float)sin(2*a));
        g_TWb[t] = make_float2((float)cos(3*a), (float)sin(3*a));
    }
}

// ---------- forward FFT: signal rows (writes both S planes, tiled layout) ----------
__global__ __launch_bounds__(512) void fft_sig(const float* __restrict__ in) {
    __shared__ float2 sm[N2];
    int row = blockIdx.x;
    const float* x = in + (long long)row * TSIG;
    for (int n = threadIdx.x; n < N2; n += 512) {
        int a0 = 2*n     - 1024;
        int a1 = 2*n + 1 - 1024;
        float re = (a0 >= 0 && a0 < TSIG) ? x[a0] : 0.f;
        float im = (a1 >= 0 && a1 < TSIG) ? x[a1] : 0.f;
        sm[n] = make_float2(re, im);
    }
    __syncthreads();
    r4_stage<5120,0>(sm); r4_stage<1280,1280>(sm); r4_stage<320,1600>(sm);
    r4_stage<80,1680>(sm); r4_stage<20,1700>(sm);  r5_stage(sm);

    int b = row >> 7, i = row & 127;
    long long base = ((long long)(b*32 + (i>>2)) * NFP) * 4 + (i & 3);
    __half2* sp1 = g_Ssp  + base;
    __half2* sp2 = g_Ssp2 + base;
    for (int k = threadIdx.x; k <= N2/2; k += 512) {
        float2 Zk = sm[pos_of_k(k)];
        float2 Zn = sm[pos_of_k(k == 0 ? 0 : N2 - k)];
        float2 A  = make_float2(Zk.x + Zn.x, Zk.y - Zn.y);
        float2 Bv = make_float2(Zk.x - Zn.x, Zk.y + Zn.y);
        float sn, cs;
        __sincosf(-6.2831853071795864769f * (float)k / (float)LFULL, &sn, &cs);
        float2 t = cmul(make_float2(cs, sn), Bv);
        float r0 = 0.5f*(A.x + t.y), i0v =  0.5f*( A.y - t.x);
        float r1 = 0.5f*(A.x - t.y), i1v =  0.5f*(-A.y - t.x);
        sp1[4LL*k]        = __floats2half2_rn(r0, i0v);
        sp1[4LL*(N2 - k)] = __floats2half2_rn(r1, i1v);
        sp2[4LL*k]        = __floats2half2_rn(i0v, -r0);
        sp2[4LL*(N2 - k)] = __floats2half2_rn(i1v, -r1);
    }
    for (int k = NF + threadIdx.x; k < NFP; k += 512) {
        sp1[4LL*k] = __floats2half2_rn(0.f, 0.f);
        sp2[4LL*k] = __floats2half2_rn(0.f, 0.f);
    }
}

// ---------- forward FFT: weight rows ----------
__global__ __launch_bounds__(512) void fft_wgt(const float* __restrict__ in) {
    __shared__ float2 sm[N2];
    int row = blockIdx.x;
    const float* x = in + (long long)row * KW;
    for (int j = threadIdx.x; j < 1280; j += 512) {
        float2 x0 = make_float2(0.f, 0.f);
        if (j < 1024) x0 = make_float2(x[2*j], x[2*j + 1]);
        float4 wa = g_TWa[j];
        float2 w3 = g_TWb[j];
        sm[j]        = x0;
        sm[j + 1280] = cmul(x0, make_float2(wa.x, wa.y));
        sm[j + 2560] = cmul(x0, make_float2(wa.z, wa.w));
        sm[j + 3840] = cmul(x0, w3);
    }
    __syncthreads();
    r4_stage<1280,1280>(sm); r4_stage<320,1600>(sm); r4_stage<80,1680>(sm);
    r4_stage<20,1700>(sm);   r5_stage(sm);

    int o = row >> 7, i = row & 127;
    __half2* sp = g_Wsp + ((long long)(o*32 + (i>>2)) * NFP) * 4 + (i & 3);
    for (int k = threadIdx.x; k <= N2/2; k += 512) {
        float2 Zk = sm[pos_of_k(k)];
        float2 Zn = sm[pos_of_k(k == 0 ? 0 : N2 - k)];
        float2 A  = make_float2(Zk.x + Zn.x, Zk.y - Zn.y);
        float2 Bv = make_float2(Zk.x - Zn.x, Zk.y + Zn.y);
        float sn, cs;
        __sincosf(-6.2831853071795864769f * (float)k / (float)LFULL, &sn, &cs);
        float2 t = cmul(make_float2(cs, sn), Bv);
        sp[4LL*k]        = __floats2half2_rn(0.5f*(A.x + t.y),  0.5f*( A.y - t.x));
        sp[4LL*(N2 - k)] = __floats2half2_rn(0.5f*(A.x - t.y),  0.5f*(-A.y - t.x));
    }
    for (int k = NF + threadIdx.x; k < NFP; k += 512)
        sp[4LL*k] = __floats2half2_rn(0.f, 0.f);
}

// ================= HMMA einsum: cp.async double-buffered =================
__device__ __forceinline__ uint32_t smem_u32(const void* p) {
    uint32_t a;
    asm("{ .reg .u64 t; cvta.to.shared.u64 t, %1; cvt.u32.u64 %0, t; }" : "=r"(a) : "l"(p));
    return a;
}
__device__ __forceinline__ void cp16(uint32_t dst, const void* src) {
    asm volatile("cp.async.cg.shared.global [%0], [%1], 16;" :: "r"(dst), "l"(src));
}

#define BUFS   98304                 // 64KB W + 32KB S per buffer
#define EIN_SMEM (2*BUFS)

__global__ __launch_bounds__(256, 1) void einsum_mma() {
    extern __shared__ __align__(1024) char smem[];
    const uint32_t sbase = smem_u32(smem);
    const int tid  = threadIdx.x;
    const int lane = tid & 31;
    const int w    = tid >> 5;          // 8 warps
    const int fl   = w >> 1;            // f within CTA
    const int m0   = (w & 1) * 64;      // o half
    const int f0   = blockIdx.x * FPB;

    // stage chunk c (32 i-channels) into buffer
    auto fill = [&](uint32_t bufb, int c) {
        #pragma unroll
        for (int it = 0; it < 16; it++) {
            int u = tid + it * 256;          // 0..4095
            int f = u & 3, ib = (u >> 2) & 7, o = u >> 5;
            const uint4* src = (const uint4*)g_Wsp + ((long long)(o*32 + c*8 + ib) * NFP + f0 + f);
            uint32_t dst = bufb + f*16384 + o*128 + ((ib*16) ^ ((o & 7) << 4));
            cp16(dst, src);
        }
        #pragma unroll
        for (int it = 0; it < 8; it++) {
            int u = tid + it * 256;          // 0..2047
            int f = u & 3, ib = (u >> 2) & 7, b = (u >> 5) & 31, pl = u >> 10;
            const uint4* bp = (const uint4*)(pl ? g_Ssp2 : g_Ssp);
            const uint4* src = bp + ((long long)(b*32 + c*8 + ib) * NFP + f0 + f);
            int n = pl*32 + b;
            uint32_t dst = bufb + 65536 + f*8192 + n*128 + ((ib*16) ^ ((n & 7) << 4));
            cp16(dst, src);
        }
        asm volatile("cp.async.commit_group;" ::: "memory");
    };

    float acc[4][8][4];
    #pragma unroll
    for (int i = 0; i < 4; i++)
        #pragma unroll
        for (int j = 0; j < 8; j++)
            #pragma unroll
            for (int q = 0; q < 4; q++) acc[i][j][q] = 0.f;

    fill(sbase, 0);
    fill(sbase + BUFS, 1);

    const uint32_t sw = (lane & 7) << 4;
    for (int c = 0; c < 4; c++) {
        if (c < 3) asm volatile("cp.async.wait_group 1;" ::: "memory");
        else       asm volatile("cp.async.wait_group 0;" ::: "memory");
        __syncthreads();

        const uint32_t bufb  = sbase + (c & 1) * BUFS;
        const uint32_t a_row = bufb + fl*16384 + (m0 + (lane & 15)) * 128;
        const uint32_t b_row = bufb + 65536 + fl*8192 + (lane & 7) * 128;

        #pragma unroll
        for (int ks = 0; ks < 4; ks++) {
            uint32_t acb = (ks*32 + (lane >> 4)*16) ^ sw;
            uint32_t bcb = (ks*32 + ((lane >> 3) & 1)*16) ^ sw;
            uint32_t bfr[8][2];
            #pragma unroll
            for (int ni = 0; ni < 8; ni++) {
                asm volatile("ldmatrix.sync.aligned.m8n8.x2.shared.b16 {%0,%1}, [%2];"
                             : "=r"(bfr[ni][0]), "=r"(bfr[ni][1])
                             : "r"(b_row + ni*1024 + bcb));
            }
            #pragma unroll
            for (int mi = 0; mi < 4; mi++) {
                uint32_t a0, a1, a2, a3;
                asm volatile("ldmatrix.sync.aligned.m8n8.x4.shared.b16 {%0,%1,%2,%3}, [%4];"
                             : "=r"(a0), "=r"(a1), "=r"(a2), "=r"(a3)
                             : "r"(a_row + mi*2048 + acb));
                #pragma unroll
                for (int ni = 0; ni < 8; ni++) {
                    asm volatile(
                        "mma.sync.aligned.m16n8k16.row.col.f32.f16.f16.f32 "
                        "{%0,%1,%2,%3}, {%4,%5,%6,%7}, {%8,%9}, {%0,%1,%2,%3};"
                        : "+f"(acc[mi][ni][0]), "+f"(acc[mi][ni][1]),
                          "+f"(acc[mi][ni][2]), "+f"(acc[mi][ni][3])
                        : "r"(a0), "r"(a1), "r"(a2), "r"(a3),
                          "r"(bfr[ni][0]), "r"(bfr[ni][1]));
                }
            }
        }
        __syncthreads();
        if (c + 2 < 4) fill(bufb, c + 2);
    }

    // ---- epilogue: 2 passes over o-halves; stage [b=32][o=64][f=4] float2 ----
    float2* stg = (float2*)smem;
    for (int p = 0; p < 2; p++) {
        if ((w & 1) == p) {
            #pragma unroll
            for (int mi = 0; mi < 4; mi++)
                #pragma unroll
                for (int ni = 0; ni < 4; ni++)
                    #pragma unroll
                    for (int j = 0; j < 4; j++) {
                        int b  = ni*8 + (lane & 3)*2 + (j & 1);
                        int ol = mi*16 + (lane >> 2) + 8*(j >> 1);
                        stg[(b*64 + ol)*4 + fl] =
                            make_float2(acc[mi][ni][j], acc[mi][ni + 4][j]);
                    }
        }
        __syncthreads();
        #pragma unroll
        for (int it = 0; it < 16; it++) {
            int u   = tid + it * 256;
            int row = u >> 1, hf = u & 1;
            int b = row >> 6, ol = row & 63;
            const uint4 v = *(const uint4*)&stg[row*4 + hf*2];
            *(uint4*)(g_Csp + (long long)(b*COUT + p*64 + ol) * NFP + f0 + hf*2) = v;
        }
        __syncthreads();
    }
}

// ---------- inverse real FFT + slice + bias ----------
__global__ __launch_bounds__(512) void ifft_kernel(const float* __restrict__ bias, float* __restrict__ out) {
    __shared__ float2 sm[N2];
    int row = blockIdx.x;
    int o   = row & 127;
    const float2* sp = g_Csp + (long long)row * NFP;

    for (int k = threadIdx.x; k < N2; k += 512) {
        float2 Xk = sp[k];
        float2 Xn = sp[N2 - k];
        float2 E  = make_float2(0.5f*(Xk.x + Xn.x), 0.5f*(Xk.y - Xn.y));
        float2 Ow = make_float2(0.5f*(Xk.x - Xn.x), 0.5f*(Xk.y + Xn.y));
        float sn, cs;
        __sincosf(6.2831853071795864769f * (float)k / (float)LFULL, &sn, &cs);
        float2 O  = cmul(Ow, make_float2(cs, sn));
        sm[k] = make_float2(E.x - O.y, -(E.y + O.x));
    }
    __syncthreads();
    r4_stage<5120,0>(sm); r4_stage<1280,1280>(sm); r4_stage<320,1600>(sm);
    r4_stage<80,1680>(sm); r4_stage<20,1700>(sm);  r5_stage(sm);

    float bo = bias[o];
    float* op = out + (long long)row * TOUT;
    const float inv = 1.0f / (float)N2;
    for (int n = threadIdx.x; n < 4097; n += 512) {
        float2 v = sm[pos_of_k(n)];
        op[2*n] = v.x * inv + bo;
        if (2*n + 1 < TOUT) op[2*n + 1] = -v.y * inv + bo;
    }
}

// ---------- launch ----------
extern "C" void kernel_launch(void* const* d_in, const int* in_sizes, int n_in,
                              void* d_out, int out_size) {
    const float* sig  = (const float*)d_in[0];
    const float* wgt  = (const float*)d_in[1];
    const float* bias = (const float*)d_in[2];
    float* out = (float*)d_out;

    cudaFuncSetAttribute(einsum_mma, cudaFuncAttributeMaxDynamicSharedMemorySize, EIN_SMEM);

    init_tw<<<7, 256>>>();
    fft_sig<<<BATCH*CIN, 512>>>(sig);
    fft_wgt<<<COUT*CIN,  512>>>(wgt);
    einsum_mma<<<NCTA, 256, EIN_SMEM>>>();
    ifft_kernel<<<BATCH*COUT, 512>>>(bias, out);
    (void)in_sizes; (void)n_in; (void)out_size;
}